// round 4
// baseline (speedup 1.0000x reference)
#include <cuda_runtime.h>
#include <math.h>

// Per-batch params: [0..63]=cos(angle), [64..127]=sin(angle), [128..191]=amplitude
__device__ float g_params[192];

// x-lerped channel-mean displacement map: [N][DH][W] floats. 1<<23 floats = 32MB cap.
#define DX_CAP (1 << 23)
__device__ float g_dx[DX_CAP];

// Fused prepass: channel-mean + bilinear x-upsample of displacement map to width W,
// plus per-batch cos/sin/amp params (block 0).
__global__ void __launch_bounds__(256) premix_kernel(
        const float* __restrict__ dmap,
        const float* __restrict__ amp,
        const float* __restrict__ ang,
        int W, int DH, int DW, int DC, int N) {
    int X  = blockIdx.x * blockDim.x + threadIdx.x;
    int dh = blockIdx.y;
    int n  = blockIdx.z;

    if (blockIdx.x == 0 && dh == 0 && n == 0 && threadIdx.x < (unsigned)N) {
        float a = ang[threadIdx.x];
        g_params[threadIdx.x]       = cosf(a);
        g_params[64 + threadIdx.x]  = sinf(a);
        g_params[128 + threadIdx.x] = amp[threadIdx.x];
    }
    if (X >= W) return;

    // half-pixel-center source x, edge clamp (matches jax bilinear resize)
    float scx = (float)DW / (float)W;
    float sx = fmaf((float)X + 0.5f, scx, -0.5f);
    float fx0 = floorf(sx);
    float wx = sx - fx0;
    int dx0 = min(max((int)fx0, 0), DW - 1);
    int dx1 = min(max((int)fx0 + 1, 0), DW - 1);

    const float* row = dmap + ((size_t)n * DH + dh) * DW * DC;
    float t0, t1;
    if (DC == 3) {
        const float* p0 = row + dx0 * 3;
        const float* p1 = row + dx1 * 3;
        t0 = (p0[0] + p0[1] + p0[2]) * (1.0f / 3.0f);
        t1 = (p1[0] + p1[1] + p1[2]) * (1.0f / 3.0f);
    } else {
        t0 = row[dx0];
        t1 = row[dx1];
    }
    // x-lerp (reference order: top = t0 + (t1-t0)*wx)
    g_dx[((size_t)n * DH + dh) * W + X] = t0 + (t1 - t0) * wx;
}

// Reflection (align_corners=False) valid for |displacement| << size:
// equivalent to reference's mod+fold for the reachable coordinate range.
__device__ __forceinline__ float reflect_small(float v, float size) {
    if (v < -0.5f)             v = -1.0f - v;
    else if (v >= size - 0.5f) v = 2.0f * size - 1.0f - v;
    return fminf(fmaxf(v, 0.0f), size - 1.0f);
}

__device__ __forceinline__ void sample_px(
        const float* __restrict__ ib, int W, int H,
        float xf, float yf, float cth, float sth, float amp, float dm,
        float fwx, float fwy,
        float& o0, float& o1, float& o2) {
    float d = dm * amp;
    float ix = fmaf(xf + cth * d, fwx, -0.5f);
    float iy = fmaf(yf + sth * d, fwy, -0.5f);
    ix = reflect_small(ix, (float)W);
    iy = reflect_small(iy, (float)H);

    float px0 = floorf(ix), py0 = floorf(iy);
    float bx = ix - px0, by = iy - py0;
    int ix0 = (int)px0;
    int iy0 = (int)py0;
    int ix1 = min(ix0 + 1, W - 1);
    int iy1 = min(iy0 + 1, H - 1);

    int ra = iy0 * (W * 3);
    int rb = iy1 * (W * 3);
    int a0 = ra + ix0 * 3;
    int a1 = ra + ix1 * 3;
    int b0 = rb + ix0 * 3;
    int b1 = rb + ix1 * 3;

    float w00 = (1.0f - bx) * (1.0f - by);
    float w01 = bx * (1.0f - by);
    float w10 = (1.0f - bx) * by;
    float w11 = bx * by;

    o0 = w00 * __ldg(ib + a0)     + w01 * __ldg(ib + a1)
       + w10 * __ldg(ib + b0)     + w11 * __ldg(ib + b1);
    o1 = w00 * __ldg(ib + a0 + 1) + w01 * __ldg(ib + a1 + 1)
       + w10 * __ldg(ib + b0 + 1) + w11 * __ldg(ib + b1 + 1);
    o2 = w00 * __ldg(ib + a0 + 2) + w01 * __ldg(ib + a1 + 2)
       + w10 * __ldg(ib + b0 + 2) + w11 * __ldg(ib + b1 + 2);
}

// 2 pixels per thread (x0 = even, x1 = x0+1).
__global__ void __launch_bounds__(256) displace_kernel(
        const float* __restrict__ img,
        float* __restrict__ out,
        int H, int W, int DH) {
    int t  = threadIdx.x;
    int x0 = (blockIdx.x * blockDim.x + t) * 2;
    int y  = blockIdx.y;
    int n  = blockIdx.z;
    if (x0 >= W) return;

    float cth = __ldg(&g_params[n]);
    float sth = __ldg(&g_params[64 + n]);
    float amp = __ldg(&g_params[128 + n]);

    // y-side of the dmap bilinear (half-pixel centers, edge clamp)
    float scy = (float)DH / (float)H;
    float sy = fmaf((float)y + 0.5f, scy, -0.5f);
    float fy0 = floorf(sy);
    float wy = sy - fy0;
    int dy0 = min(max((int)fy0, 0), DH - 1);
    int dy1 = min(max((int)fy0 + 1, 0), DH - 1);

    const float* ib = img + (size_t)n * H * W * 3;
    float fwx = (float)W / (float)(W - 1);
    float fwy = (float)H / (float)(H - 1);

    if (x0 + 1 < W) {
        // x-lerped dmap rows: float2 covering (x0, x0+1)
        const float2* r0 = (const float2*)(g_dx + ((size_t)n * DH + dy0) * W + x0);
        const float2* r1 = (const float2*)(g_dx + ((size_t)n * DH + dy1) * W + x0);
        float2 xa = __ldg(r0);
        float2 xb = __ldg(r1);
        float dmA = xa.x + (xb.x - xa.x) * wy;
        float dmB = xa.y + (xb.y - xa.y) * wy;

        float a0, a1, a2, c0, c1, c2;
        sample_px(ib, W, H, (float)x0,       (float)y, cth, sth, amp, dmA, fwx, fwy, a0, a1, a2);
        sample_px(ib, W, H, (float)(x0 + 1), (float)y, cth, sth, amp, dmB, fwx, fwy, c0, c1, c2);

        // 6 consecutive floats, 8B-aligned (x0 even, row base even) -> 3 STG.64
        float2* o2p = (float2*)(out + ((size_t)(n * H + y) * W + x0) * 3);
        o2p[0] = make_float2(a0, a1);
        o2p[1] = make_float2(a2, c0);
        o2p[2] = make_float2(c1, c2);
    } else {
        // tail pixel (odd W)
        float xl0 = __ldg(g_dx + ((size_t)n * DH + dy0) * W + x0);
        float xl1 = __ldg(g_dx + ((size_t)n * DH + dy1) * W + x0);
        float dm = xl0 + (xl1 - xl0) * wy;
        float a0, a1, a2;
        sample_px(ib, W, H, (float)x0, (float)y, cth, sth, amp, dm, fwx, fwy, a0, a1, a2);
        float* op = out + ((size_t)(n * H + y) * W + x0) * 3;
        op[0] = a0; op[1] = a1; op[2] = a2;
    }
}

extern "C" void kernel_launch(void* const* d_in, const int* in_sizes, int n_in,
                              void* d_out, int out_size) {
    const float* img  = (const float*)d_in[0];
    const float* dmap = (const float*)d_in[1];
    const float* amp  = (const float*)d_in[2];
    const float* ang  = (const float*)d_in[3];
    float* out = (float*)d_out;

    int N = in_sizes[2];
    long long ipix = (long long)in_sizes[0] / ((long long)N * 3);
    int H = (int)(sqrt((double)ipix) + 0.5);
    int W = H;

    int DC = 3;
    long long dpix = (long long)in_sizes[1] / ((long long)N * 3);
    int DH = (int)(sqrt((double)dpix) + 0.5);
    if ((long long)DH * DH != dpix) {
        DC = 1;
        dpix = (long long)in_sizes[1] / N;
        DH = (int)(sqrt((double)dpix) + 0.5);
    }
    int DW = DH;

    // Prepass: params + x-lerped mean dmap at width W  (N*DH*W floats, fits DX_CAP)
    dim3 pblock(256, 1, 1);
    dim3 pgrid((W + 255) / 256, DH, N);
    premix_kernel<<<pgrid, pblock>>>(dmap, amp, ang, W, DH, DW, DC, N);

    // Main: 2 px/thread
    int pairs = (W + 1) / 2;
    dim3 block(256, 1, 1);
    dim3 grid((pairs + 255) / 256, H, N);
    displace_kernel<<<grid, block>>>(img, out, H, W, DH);
}

// round 10
// speedup vs baseline: 1.0684x; 1.0684x over previous
#include <cuda_runtime.h>
#include <math.h>

// Per-batch params: [0..63]=cos(angle), [64..127]=sin(angle), [128..191]=amplitude
__device__ float g_params[192];

// Channel-mean displacement map scratch (N*DH*DW floats). 32MB cap.
#define DMEAN_CAP (1 << 23)
__device__ float g_dmean[DMEAN_CAP];

// Fused prepass: channel-mean of dmap (float4 path) + per-batch cos/sin/amp.
__global__ void __launch_bounds__(256) mean_kernel(
        const float* __restrict__ dmap,
        const float* __restrict__ amp,
        const float* __restrict__ ang,
        int total, int DC, int N) {
    if (blockIdx.x == 0 && threadIdx.x < (unsigned)N) {
        float a = ang[threadIdx.x];
        g_params[threadIdx.x]       = cosf(a);
        g_params[64 + threadIdx.x]  = sinf(a);
        g_params[128 + threadIdx.x] = amp[threadIdx.x];
    }
    int q = blockIdx.x * blockDim.x + threadIdx.x;
    int t0 = q * 4;
    if (t0 >= total) return;
    if (t0 + 4 <= total) {
        if (DC == 3) {
            const float4* p = (const float4*)(dmap + (size_t)t0 * 3);
            float4 a = p[0], b = p[1], c = p[2];
            const float k = 1.0f / 3.0f;
            float4 m;
            m.x = (a.x + a.y + a.z) * k;
            m.y = (a.w + b.x + b.y) * k;
            m.z = (b.z + b.w + c.x) * k;
            m.w = (c.y + c.z + c.w) * k;
            *(float4*)(g_dmean + t0) = m;
        } else {
            *(float4*)(g_dmean + t0) = *(const float4*)(dmap + t0);
        }
    } else {
        for (int t = t0; t < total; t++) {
            if (DC == 3)
                g_dmean[t] = (dmap[t*3] + dmap[t*3+1] + dmap[t*3+2]) * (1.0f / 3.0f);
            else
                g_dmean[t] = dmap[t];
        }
    }
}

// Reflection (align_corners=False), valid for the reachable coordinate range
// (|displacement| << size): equivalent to the reference's mod+fold.
__device__ __forceinline__ float reflect_small(float v, float size) {
    if (v < -0.5f)             v = -1.0f - v;
    else if (v >= size - 0.5f) v = 2.0f * size - 1.0f - v;
    return fminf(fmaxf(v, 0.0f), size - 1.0f);
}

// Load one bilinear tap-row: pixels (ix0, ix0+1) = 6 consecutive floats at
// float index rowOff + 3*ix0 (relative to ib). Wide path: 4x LDG.64 from an
// 8B-aligned base + SEL extraction. The extra trailing floats read stay
// inside the buffer (limit8 guard); where they'd cross the end we fall back
// to scalar clamped loads. At row end the ix1 tap has weight bx==0, so the
// values read there never affect the output.
__device__ __forceinline__ void load_taprow(
        const float* __restrict__ ib, long long rowOff, int ix0, int W,
        long long limit8,
        float& r0, float& r1, float& r2, float& r3, float& r4, float& r5) {
    int off = 3 * ix0;
    long long idx = rowOff + (off & ~1);
    int s = off & 1;
    if (idx <= limit8) {
        const float2* p = (const float2*)(ib + idx);
        float2 l0 = __ldg(p), l1 = __ldg(p + 1), l2 = __ldg(p + 2), l3 = __ldg(p + 3);
        float g0 = l0.x, g1 = l0.y, g2 = l1.x, g3 = l1.y;
        float g4 = l2.x, g5 = l2.y, g6 = l3.x;
        r0 = s ? g1 : g0;
        r1 = s ? g2 : g1;
        r2 = s ? g3 : g2;
        r3 = s ? g4 : g3;
        r4 = s ? g5 : g4;
        r5 = s ? g6 : g5;
    } else {
        int ix1 = min(ix0 + 1, W - 1);
        const float* pa = ib + rowOff + 3 * ix0;
        const float* pb = ib + rowOff + 3 * ix1;
        r0 = __ldg(pa); r1 = __ldg(pa + 1); r2 = __ldg(pa + 2);
        r3 = __ldg(pb); r4 = __ldg(pb + 1); r5 = __ldg(pb + 2);
    }
}

__global__ void __launch_bounds__(256) displace_kernel(
        const float* __restrict__ img,
        float* __restrict__ out,
        int H, int W, int DH, int DW, int N) {
    int x = blockIdx.x * blockDim.x + threadIdx.x;
    int y = blockIdx.y;
    int n = blockIdx.z;
    if (x >= W) return;

    float cth = __ldg(&g_params[n]);
    float sth = __ldg(&g_params[64 + n]);
    float amp = __ldg(&g_params[128 + n]);

    // ---- 1. bilinear sample of mean displacement map (half-pixel, edge clamp) ----
    float scx = (float)DW / (float)W;
    float scy = (float)DH / (float)H;
    float sx = fmaf((float)x + 0.5f, scx, -0.5f);
    float sy = fmaf((float)y + 0.5f, scy, -0.5f);
    float fx0 = floorf(sx), fy0 = floorf(sy);
    float wx = sx - fx0, wy = sy - fy0;
    int dx0 = min(max((int)fx0, 0), DW - 1);
    int dx1 = min(max((int)fx0 + 1, 0), DW - 1);
    int dy0 = min(max((int)fy0, 0), DH - 1);
    int dy1 = min(max((int)fy0 + 1, 0), DH - 1);

    const float* db = g_dmean + n * DH * DW;
    const float* dr0 = db + dy0 * DW;
    const float* dr1 = db + dy1 * DW;
    float t00 = __ldg(dr0 + dx0), t01 = __ldg(dr0 + dx1);
    float t10 = __ldg(dr1 + dx0), t11 = __ldg(dr1 + dx1);
    float top = t00 + (t01 - t00) * wx;
    float bot = t10 + (t11 - t10) * wx;
    float dm  = top + (bot - top) * wy;

    // ---- 2. sampling position (collapsed algebra) ----
    float d = dm * amp;
    float fwx = (float)W / (float)(W - 1);
    float fwy = (float)H / (float)(H - 1);
    float ix = fmaf((float)x + cth * d, fwx, -0.5f);
    float iy = fmaf((float)y + sth * d, fwy, -0.5f);
    ix = reflect_small(ix, (float)W);
    iy = reflect_small(iy, (float)H);

    // ---- 3. bilinear gather (wide tap-row loads) ----
    float px0 = floorf(ix), py0 = floorf(iy);
    float bx = ix - px0, by = iy - py0;
    int ix0 = (int)px0;
    int iy0 = (int)py0;
    int iy1 = min(iy0 + 1, H - 1);

    const float* ib = img + (size_t)n * H * W * 3;
    long long hw3 = (long long)H * W * 3;
    // Floats remaining in the whole image buffer after ib, minus the 8-float
    // wide-read window.
    long long limit8 = (long long)(N - n) * hw3 - 8;

    long long rowA = (long long)iy0 * (W * 3);
    long long rowB = (long long)iy1 * (W * 3);

    float a0, a1, a2, a3, a4, a5;
    float b0, b1, b2, b3, b4, b5;
    load_taprow(ib, rowA, ix0, W, limit8, a0, a1, a2, a3, a4, a5);
    load_taprow(ib, rowB, ix0, W, limit8, b0, b1, b2, b3, b4, b5);

    float w00 = (1.0f - bx) * (1.0f - by);
    float w01 = bx * (1.0f - by);
    float w10 = (1.0f - bx) * by;
    float w11 = bx * by;

    float o0 = w00 * a0 + w01 * a3 + w10 * b0 + w11 * b3;
    float o1 = w00 * a1 + w01 * a4 + w10 * b1 + w11 * b4;
    float o2 = w00 * a2 + w01 * a5 + w10 * b2 + w11 * b5;

    size_t obase = ((size_t)(n * H + y) * W + x) * 3;
    out[obase + 0] = o0;
    out[obase + 1] = o1;
    out[obase + 2] = o2;
}

extern "C" void kernel_launch(void* const* d_in, const int* in_sizes, int n_in,
                              void* d_out, int out_size) {
    const float* img  = (const float*)d_in[0];
    const float* dmap = (const float*)d_in[1];
    const float* amp  = (const float*)d_in[2];
    const float* ang  = (const float*)d_in[3];
    float* out = (float*)d_out;

    int N = in_sizes[2];
    long long ipix = (long long)in_sizes[0] / ((long long)N * 3);
    int H = (int)(sqrt((double)ipix) + 0.5);
    int W = H;

    int DC = 3;
    long long dpix = (long long)in_sizes[1] / ((long long)N * 3);
    int DH = (int)(sqrt((double)dpix) + 0.5);
    if ((long long)DH * DH != dpix) {
        DC = 1;
        dpix = (long long)in_sizes[1] / N;
        DH = (int)(sqrt((double)dpix) + 0.5);
    }
    int DW = DH;

    int total = N * DH * DW;  // 2M floats here, fits DMEAN_CAP
    int quads = (total + 3) / 4;
    mean_kernel<<<(quads + 255) / 256, 256>>>(dmap, amp, ang, total, DC, N);

    dim3 block(256, 1, 1);
    dim3 grid((W + block.x - 1) / block.x, H, N);
    displace_kernel<<<grid, block>>>(img, out, H, W, DH, DW, N);
}

// round 13
// speedup vs baseline: 1.1447x; 1.0714x over previous
#include <cuda_runtime.h>
#include <math.h>

// Per-batch params: [0..63]=cos(angle), [64..127]=sin(angle), [128..191]=amplitude
__device__ float g_params[192];

// Channel-mean displacement map (N*DH*DW floats), 8MB here.
#define DMEAN_CAP (1 << 21)
__device__ float g_dmean[DMEAN_CAP];

// x-upsampled (x-lerped) mean dmap at full width: [N][DH][W], 16.8MB here.
#define DX_CAP (1 << 23)
__device__ float g_dx[DX_CAP];

// ---- Stage 1: channel-mean of dmap (float4 path) + per-batch cos/sin/amp ----
__global__ void __launch_bounds__(256) mean_kernel(
        const float* __restrict__ dmap,
        const float* __restrict__ amp,
        const float* __restrict__ ang,
        int total, int DC, int N) {
    if (blockIdx.x == 0 && threadIdx.x < (unsigned)N) {
        float a = ang[threadIdx.x];
        g_params[threadIdx.x]       = cosf(a);
        g_params[64 + threadIdx.x]  = sinf(a);
        g_params[128 + threadIdx.x] = amp[threadIdx.x];
    }
    int q = blockIdx.x * blockDim.x + threadIdx.x;
    int t0 = q * 4;
    if (t0 >= total) return;
    if (t0 + 4 <= total) {
        if (DC == 3) {
            const float4* p = (const float4*)(dmap + (size_t)t0 * 3);
            float4 a = p[0], b = p[1], c = p[2];
            const float k = 1.0f / 3.0f;
            float4 m;
            m.x = (a.x + a.y + a.z) * k;
            m.y = (a.w + b.x + b.y) * k;
            m.z = (b.z + b.w + c.x) * k;
            m.w = (c.y + c.z + c.w) * k;
            *(float4*)(g_dmean + t0) = m;
        } else {
            *(float4*)(g_dmean + t0) = *(const float4*)(dmap + t0);
        }
    } else {
        for (int t = t0; t < total; t++) {
            if (DC == 3)
                g_dmean[t] = (dmap[t*3] + dmap[t*3+1] + dmap[t*3+2]) * (1.0f / 3.0f);
            else
                g_dmean[t] = dmap[t];
        }
    }
}

// ---- Stage 2: x-upsample mean dmap to width W (half-pixel centers, clamp) ----
__global__ void __launch_bounds__(256) xup_kernel(
        int W, int DH, int DW, float scx) {
    int X  = blockIdx.x * blockDim.x + threadIdx.x;
    int dh = blockIdx.y;
    int n  = blockIdx.z;
    if (X >= W) return;
    float sx = fmaf((float)X + 0.5f, scx, -0.5f);
    float fx0 = floorf(sx);
    float wx = sx - fx0;
    int f = (int)fx0;                       // floorf already applied; safe cast
    int dx0 = min(max(f, 0), DW - 1);       // reference clamp: both taps clamped
    int dx1 = min(max(f + 1, 0), DW - 1);   //   independently from f and f+1
    const float* row = g_dmean + (n * DH + dh) * DW;
    float t0 = __ldg(row + dx0);
    float t1 = __ldg(row + dx1);
    g_dx[(n * DH + dh) * W + X] = t0 + (t1 - t0) * wx;  // reference lerp order
}

// Branchless reflection (align_corners=False), exact over the reachable range
// (|displacement| << size): fold about -0.5 and size-0.5, then clamp.
__device__ __forceinline__ float reflect_small(float v, float size) {
    v = fabsf(v + 0.5f) - 0.5f;                    // left fold about -0.5
    float e = size - 0.5f;
    v = e - fabsf(v - e);                          // right fold about size-0.5
    return fminf(fmaxf(v, 0.0f), size - 1.0f);
}

// ---- Stage 3: displace ----
__global__ void __launch_bounds__(256) displace_kernel(
        const float* __restrict__ img,
        float* __restrict__ out,
        int H, int W, int DH, int W3,
        float scy, float fwx, float fwy, int totalFloats) {
    int x = blockIdx.x * blockDim.x + threadIdx.x;
    int y = blockIdx.y;
    int n = blockIdx.z;
    if (x >= W) return;

    float cth = __ldg(&g_params[n]);
    float sth = __ldg(&g_params[64 + n]);
    float amp = __ldg(&g_params[128 + n]);

    // ---- dmap y-lerp (x-lerp precomputed in g_dx) ----
    float sy = fmaf((float)y + 0.5f, scy, -0.5f);
    float fy0 = floorf(sy);
    float wy = sy - fy0;
    int fy = (int)fy0;
    int dy0 = min(max(fy, 0), DH - 1);      // reference clamp (independent taps)
    int dy1 = min(max(fy + 1, 0), DH - 1);

    const float* dxb = g_dx + n * DH * W + x;
    float m0 = __ldg(dxb + dy0 * W);
    float m1 = __ldg(dxb + dy1 * W);
    float dm = m0 + (m1 - m0) * wy;

    // ---- sampling position ----
    float d = dm * amp;
    float ix = fmaf((float)x + cth * d, fwx, -0.5f);
    float iy = fmaf((float)y + sth * d, fwy, -0.5f);
    ix = reflect_small(ix, (float)W);
    iy = reflect_small(iy, (float)H);

    float px0 = floorf(ix), py0 = floorf(iy);
    float bx = ix - px0, by = iy - py0;
    int ix0 = (int)px0;                     // in [0, W-1] after reflect+clip
    int iy0 = (int)py0;
    int iy1 = min(iy0 + 1, H - 1);          // iy0 >= 0 here, so this matches ref

    // ---- bilinear gather: wide tap-row loads, single bounds check ----
    int nOff = n * H * W3;            // all offsets fit int32 (totalFloats < 2^31)
    int off  = 3 * ix0;
    int offe = off & ~1;
    int s    = off & 1;
    int idxA = nOff + iy0 * W3 + offe;
    int idxB = nOff + iy1 * W3 + offe;

    float a0, a1, a2, a3, a4, a5;
    float b0, b1, b2, b3, b4, b5;
    if (idxB + 8 <= totalFloats) {    // idxB >= idxA, so both windows in-bounds
        const float2* pA = (const float2*)(img + idxA);
        const float2* pB = (const float2*)(img + idxB);
        float2 A0 = __ldg(pA), A1 = __ldg(pA + 1), A2 = __ldg(pA + 2), A3 = __ldg(pA + 3);
        float2 B0 = __ldg(pB), B1 = __ldg(pB + 1), B2 = __ldg(pB + 2), B3 = __ldg(pB + 3);
        a0 = s ? A0.y : A0.x;  a1 = s ? A1.x : A0.y;  a2 = s ? A1.y : A1.x;
        a3 = s ? A2.x : A1.y;  a4 = s ? A2.y : A2.x;  a5 = s ? A3.x : A2.y;
        b0 = s ? B0.y : B0.x;  b1 = s ? B1.x : B0.y;  b2 = s ? B1.y : B1.x;
        b3 = s ? B2.x : B1.y;  b4 = s ? B2.y : B2.x;  b5 = s ? B3.x : B2.y;
        // At ix0 == W-1 the second tap (a3..a5/b3..b5) reads the next row,
        // but bx == 0 there (ix <= W-1 post-clip), so its weight is exactly 0.
    } else {
        int ix1 = min(ix0 + 1, W - 1);
        const float* pa = img + nOff + iy0 * W3 + 3 * ix0;
        const float* pc = img + nOff + iy0 * W3 + 3 * ix1;
        const float* pb = img + nOff + iy1 * W3 + 3 * ix0;
        const float* pd = img + nOff + iy1 * W3 + 3 * ix1;
        a0 = __ldg(pa); a1 = __ldg(pa + 1); a2 = __ldg(pa + 2);
        a3 = __ldg(pc); a4 = __ldg(pc + 1); a5 = __ldg(pc + 2);
        b0 = __ldg(pb); b1 = __ldg(pb + 1); b2 = __ldg(pb + 2);
        b3 = __ldg(pd); b4 = __ldg(pd + 1); b5 = __ldg(pd + 2);
    }

    float w00 = (1.0f - bx) * (1.0f - by);
    float w01 = bx * (1.0f - by);
    float w10 = (1.0f - bx) * by;
    float w11 = bx * by;

    float o0 = w00 * a0 + w01 * a3 + w10 * b0 + w11 * b3;
    float o1 = w00 * a1 + w01 * a4 + w10 * b1 + w11 * b4;
    float o2 = w00 * a2 + w01 * a5 + w10 * b2 + w11 * b5;

    int obase = (n * H + y) * W3 + 3 * x;
    out[obase + 0] = o0;
    out[obase + 1] = o1;
    out[obase + 2] = o2;
}

extern "C" void kernel_launch(void* const* d_in, const int* in_sizes, int n_in,
                              void* d_out, int out_size) {
    const float* img  = (const float*)d_in[0];
    const float* dmap = (const float*)d_in[1];
    const float* amp  = (const float*)d_in[2];
    const float* ang  = (const float*)d_in[3];
    float* out = (float*)d_out;

    int N = in_sizes[2];
    long long ipix = (long long)in_sizes[0] / ((long long)N * 3);
    int H = (int)(sqrt((double)ipix) + 0.5);
    int W = H;

    int DC = 3;
    long long dpix = (long long)in_sizes[1] / ((long long)N * 3);
    int DH = (int)(sqrt((double)dpix) + 0.5);
    if ((long long)DH * DH != dpix) {
        DC = 1;
        dpix = (long long)in_sizes[1] / N;
        DH = (int)(sqrt((double)dpix) + 0.5);
    }
    int DW = DH;

    // Stage 1: mean + params
    int total = N * DH * DW;   // 2M floats here, fits DMEAN_CAP
    int quads = (total + 3) / 4;
    mean_kernel<<<(quads + 255) / 256, 256>>>(dmap, amp, ang, total, DC, N);

    // Stage 2: x-upsample to width W
    float scx = (float)DW / (float)W;
    dim3 xgrid((W + 255) / 256, DH, N);
    xup_kernel<<<xgrid, 256>>>(W, DH, DW, scx);

    // Stage 3: displace
    float scy = (float)DH / (float)H;
    float fwx = (float)W / (float)(W - 1);
    float fwy = (float)H / (float)(H - 1);
    int W3 = W * 3;
    int totalFloats = N * H * W3;
    dim3 grid((W + 255) / 256, H, N);
    displace_kernel<<<grid, 256>>>(img, out, H, W, DH, W3, scy, fwx, fwy, totalFloats);
}

// round 15
// speedup vs baseline: 1.2935x; 1.1300x over previous
#include <cuda_runtime.h>
#include <math.h>

// Per-batch params: [0..63]=cos(angle), [64..127]=sin(angle), [128..191]=amplitude
__device__ float g_params[192];

// Channel-mean dmap (fallback path only): N*DH*DW floats.
#define DMEAN_CAP (1 << 21)
__device__ float g_dmean[DMEAN_CAP];

// x-upsampled (x-lerped) mean dmap at full width: [N][DH][W].
#define DX_CAP (1 << 23)
__device__ float g_dx[DX_CAP];

// ---- Fused prepass: per-row channel-mean (smem) + x-upsample + params ----
// Grid: (DH, N). Requires DW <= 1024 and (DW*DC)%4 == 0 (16B-aligned rows).
__global__ void __launch_bounds__(256) fused_prep_kernel(
        const float* __restrict__ dmap,
        const float* __restrict__ amp,
        const float* __restrict__ ang,
        int W, int DH, int DW, int DC, int N, float scx) {
    __shared__ float s_mean[1024];
    int dh = blockIdx.x;
    int n  = blockIdx.y;
    int tid = threadIdx.x;

    if (dh == 0 && n == 0 && tid < (unsigned)N) {
        float a = ang[tid];
        g_params[tid]       = cosf(a);
        g_params[64 + tid]  = sinf(a);
        g_params[128 + tid] = amp[tid];
    }

    // Phase 1: channel-mean of this dmap row into smem.
    const float* row = dmap + (size_t)(n * DH + dh) * DW * DC;
    if (DC == 3) {
        int groups = DW >> 2;       // 4 pixels = 3 float4s per group
        for (int g = tid; g < groups; g += 256) {
            const float4* p = (const float4*)(row + g * 12);
            float4 a = __ldg(p), b = __ldg(p + 1), c = __ldg(p + 2);
            const float k = 1.0f / 3.0f;
            int o = g * 4;
            s_mean[o + 0] = (a.x + a.y + a.z) * k;
            s_mean[o + 1] = (a.w + b.x + b.y) * k;
            s_mean[o + 2] = (b.z + b.w + c.x) * k;
            s_mean[o + 3] = (c.y + c.z + c.w) * k;
        }
        for (int p = (groups << 2) + tid; p < DW; p += 256)
            s_mean[p] = (row[p*3] + row[p*3+1] + row[p*3+2]) * (1.0f / 3.0f);
    } else {
        for (int p = tid; p < DW; p += 256)
            s_mean[p] = row[p];
    }
    __syncthreads();

    // Phase 2: x-lerp to width W, float4 stores.
    float* orow = g_dx + (size_t)(n * DH + dh) * W;
    for (int X0 = tid * 4; X0 < W; X0 += 1024) {
        if (X0 + 4 <= W) {
            float4 v;
            float* vp = (float*)&v;
            #pragma unroll
            for (int j = 0; j < 4; j++) {
                int X = X0 + j;
                float sx = fmaf((float)X + 0.5f, scx, -0.5f);
                float fx0 = floorf(sx);
                float wx = sx - fx0;
                int f = (int)fx0;
                int dx0 = min(max(f, 0), DW - 1);
                int dx1 = min(max(f + 1, 0), DW - 1);
                float t0 = s_mean[dx0], t1 = s_mean[dx1];
                vp[j] = t0 + (t1 - t0) * wx;
            }
            *(float4*)(orow + X0) = v;
        } else {
            for (int X = X0; X < W; X++) {
                float sx = fmaf((float)X + 0.5f, scx, -0.5f);
                float fx0 = floorf(sx);
                float wx = sx - fx0;
                int f = (int)fx0;
                int dx0 = min(max(f, 0), DW - 1);
                int dx1 = min(max(f + 1, 0), DW - 1);
                float t0 = s_mean[dx0], t1 = s_mean[dx1];
                orow[X] = t0 + (t1 - t0) * wx;
            }
        }
    }
}

// ---- Fallback prepass (generic shapes): mean then xup ----
__global__ void __launch_bounds__(256) mean_kernel(
        const float* __restrict__ dmap,
        const float* __restrict__ amp,
        const float* __restrict__ ang,
        int total, int DC, int N) {
    if (blockIdx.x == 0 && threadIdx.x < (unsigned)N) {
        float a = ang[threadIdx.x];
        g_params[threadIdx.x]       = cosf(a);
        g_params[64 + threadIdx.x]  = sinf(a);
        g_params[128 + threadIdx.x] = amp[threadIdx.x];
    }
    int t = blockIdx.x * blockDim.x + threadIdx.x;
    if (t >= total) return;
    if (DC == 3)
        g_dmean[t] = (dmap[t*3] + dmap[t*3+1] + dmap[t*3+2]) * (1.0f / 3.0f);
    else
        g_dmean[t] = dmap[t];
}

__global__ void __launch_bounds__(256) xup_kernel(
        int W, int DH, int DW, float scx) {
    int X  = blockIdx.x * blockDim.x + threadIdx.x;
    int dh = blockIdx.y;
    int n  = blockIdx.z;
    if (X >= W) return;
    float sx = fmaf((float)X + 0.5f, scx, -0.5f);
    float fx0 = floorf(sx);
    float wx = sx - fx0;
    int f = (int)fx0;
    int dx0 = min(max(f, 0), DW - 1);
    int dx1 = min(max(f + 1, 0), DW - 1);
    const float* row = g_dmean + (n * DH + dh) * DW;
    float t0 = __ldg(row + dx0);
    float t1 = __ldg(row + dx1);
    g_dx[(n * DH + dh) * W + X] = t0 + (t1 - t0) * wx;
}

// Branchless reflection (align_corners=False), exact over the reachable range.
__device__ __forceinline__ float reflect_small(float v, float size) {
    v = fabsf(v + 0.5f) - 0.5f;
    float e = size - 0.5f;
    v = e - fabsf(v - e);
    return fminf(fmaxf(v, 0.0f), size - 1.0f);
}

// One pixel of the displace: dmap y-lerp, position, reflect, gather, store.
__device__ __forceinline__ void displace_px(
        const float* __restrict__ img, float* __restrict__ out,
        int x, int y, int n, int H, int W, int DH, int W3,
        float scy, float fwx, float fwy, int totalFloats,
        float cth, float sth, float amp, const float* __restrict__ dxcol) {
    // dmap y-lerp (x-lerp precomputed; dxcol = g_dx + n*DH*W + x)
    float sy = fmaf((float)y + 0.5f, scy, -0.5f);
    float fy0 = floorf(sy);
    float wy = sy - fy0;
    int fy = (int)fy0;
    int dy0 = min(max(fy, 0), DH - 1);
    int dy1 = min(max(fy + 1, 0), DH - 1);
    float m0 = __ldg(dxcol + dy0 * W);
    float m1 = __ldg(dxcol + dy1 * W);
    float dm = m0 + (m1 - m0) * wy;

    // sampling position
    float d = dm * amp;
    float ix = fmaf((float)x + cth * d, fwx, -0.5f);
    float iy = fmaf((float)y + sth * d, fwy, -0.5f);
    ix = reflect_small(ix, (float)W);
    iy = reflect_small(iy, (float)H);

    float px0 = floorf(ix), py0 = floorf(iy);
    float bx = ix - px0, by = iy - py0;
    int ix0 = (int)px0;
    int iy0 = (int)py0;
    int iy1 = min(iy0 + 1, H - 1);

    // gather: wide tap-row loads, single bounds check
    int nOff = n * H * W3;
    int off  = 3 * ix0;
    int offe = off & ~1;
    int s    = off & 1;
    int idxA = nOff + iy0 * W3 + offe;
    int idxB = nOff + iy1 * W3 + offe;

    float a0, a1, a2, a3, a4, a5;
    float b0, b1, b2, b3, b4, b5;
    if (idxB + 8 <= totalFloats) {
        const float2* pA = (const float2*)(img + idxA);
        const float2* pB = (const float2*)(img + idxB);
        float2 A0 = __ldg(pA), A1 = __ldg(pA + 1), A2 = __ldg(pA + 2), A3 = __ldg(pA + 3);
        float2 B0 = __ldg(pB), B1 = __ldg(pB + 1), B2 = __ldg(pB + 2), B3 = __ldg(pB + 3);
        a0 = s ? A0.y : A0.x;  a1 = s ? A1.x : A0.y;  a2 = s ? A1.y : A1.x;
        a3 = s ? A2.x : A1.y;  a4 = s ? A2.y : A2.x;  a5 = s ? A3.x : A2.y;
        b0 = s ? B0.y : B0.x;  b1 = s ? B1.x : B0.y;  b2 = s ? B1.y : B1.x;
        b3 = s ? B2.x : B1.y;  b4 = s ? B2.y : B2.x;  b5 = s ? B3.x : B2.y;
        // At ix0 == W-1 the second tap has weight bx == 0, so the values it
        // reads (next row) never affect the output.
    } else {
        int ix1 = min(ix0 + 1, W - 1);
        const float* pa = img + nOff + iy0 * W3 + 3 * ix0;
        const float* pc = img + nOff + iy0 * W3 + 3 * ix1;
        const float* pb = img + nOff + iy1 * W3 + 3 * ix0;
        const float* pd = img + nOff + iy1 * W3 + 3 * ix1;
        a0 = __ldg(pa); a1 = __ldg(pa + 1); a2 = __ldg(pa + 2);
        a3 = __ldg(pc); a4 = __ldg(pc + 1); a5 = __ldg(pc + 2);
        b0 = __ldg(pb); b1 = __ldg(pb + 1); b2 = __ldg(pb + 2);
        b3 = __ldg(pd); b4 = __ldg(pd + 1); b5 = __ldg(pd + 2);
    }

    float w00 = (1.0f - bx) * (1.0f - by);
    float w01 = bx * (1.0f - by);
    float w10 = (1.0f - bx) * by;
    float w11 = bx * by;

    float o0 = w00 * a0 + w01 * a3 + w10 * b0 + w11 * b3;
    float o1 = w00 * a1 + w01 * a4 + w10 * b1 + w11 * b4;
    float o2 = w00 * a2 + w01 * a5 + w10 * b2 + w11 * b5;

    int obase = (n * H + y) * W3 + 3 * x;
    out[obase + 0] = o0;
    out[obase + 1] = o1;
    out[obase + 2] = o2;
}

// ---- Displace: 2 pixels per thread, split in y (disjoint gather rows) ----
__global__ void __launch_bounds__(256) displace_kernel(
        const float* __restrict__ img,
        float* __restrict__ out,
        int H, int W, int DH, int W3, int halfH,
        float scy, float fwx, float fwy, int totalFloats) {
    int x  = blockIdx.x * blockDim.x + threadIdx.x;
    int y0 = blockIdx.y;
    int n  = blockIdx.z;
    if (x >= W) return;

    float cth = __ldg(&g_params[n]);
    float sth = __ldg(&g_params[64 + n]);
    float amp = __ldg(&g_params[128 + n]);
    const float* dxcol = g_dx + n * DH * W + x;

    displace_px(img, out, x, y0, n, H, W, DH, W3,
                scy, fwx, fwy, totalFloats, cth, sth, amp, dxcol);
    int y1 = y0 + halfH;
    if (y1 < H)
        displace_px(img, out, x, y1, n, H, W, DH, W3,
                    scy, fwx, fwy, totalFloats, cth, sth, amp, dxcol);
}

extern "C" void kernel_launch(void* const* d_in, const int* in_sizes, int n_in,
                              void* d_out, int out_size) {
    const float* img  = (const float*)d_in[0];
    const float* dmap = (const float*)d_in[1];
    const float* amp  = (const float*)d_in[2];
    const float* ang  = (const float*)d_in[3];
    float* out = (float*)d_out;

    int N = in_sizes[2];
    long long ipix = (long long)in_sizes[0] / ((long long)N * 3);
    int H = (int)(sqrt((double)ipix) + 0.5);
    int W = H;

    int DC = 3;
    long long dpix = (long long)in_sizes[1] / ((long long)N * 3);
    int DH = (int)(sqrt((double)dpix) + 0.5);
    if ((long long)DH * DH != dpix) {
        DC = 1;
        dpix = (long long)in_sizes[1] / N;
        DH = (int)(sqrt((double)dpix) + 0.5);
    }
    int DW = DH;

    float scx = (float)DW / (float)W;

    if (DW <= 1024 && ((DW * DC) % 4 == 0) && (DC == 1 || DC == 3)) {
        dim3 fgrid(DH, N);
        fused_prep_kernel<<<fgrid, 256>>>(dmap, amp, ang, W, DH, DW, DC, N, scx);
    } else {
        int total = N * DH * DW;
        mean_kernel<<<(total + 255) / 256, 256>>>(dmap, amp, ang, total, DC, N);
        dim3 xgrid((W + 255) / 256, DH, N);
        xup_kernel<<<xgrid, 256>>>(W, DH, DW, scx);
    }

    float scy = (float)DH / (float)H;
    float fwx = (float)W / (float)(W - 1);
    float fwy = (float)H / (float)(H - 1);
    int W3 = W * 3;
    int totalFloats = N * H * W3;
    int halfH = (H + 1) / 2;
    dim3 grid((W + 255) / 256, halfH, N);
    displace_kernel<<<grid, 256>>>(img, out, H, W, DH, W3, halfH,
                                   scy, fwx, fwy, totalFloats);
}